// round 13
// baseline (speedup 1.0000x reference)
#include <cuda_runtime.h>
#include <cuda_bf16.h>
#include <cstdint>
#include <cstddef>

// ---------------------------------------------------------------------------
// SemRelAttention, HMMA everywhere:
//   convert_w / rel_build : weights + rel tables -> bf16 hi/lo
//   dwt(x,dw1)            : fused dw3x3 + bf16 split + transpose -> g_bT
//   gemm_mma pw1 : 8-stage split; Q tiles (mtb<2) write DIRECTLY to qTh/qTl
//   pool_kv               : bf16 split K,V
//   attn (256 thr, QK mma + rel mma + softmax + AV mma) -> attn region + y2
//   dwt(y2,dw2) -> g_bT ; gemm_mma pw2 -> out region
// d_out = [ out : 4*256*128*128 | attn : 4*4*16384*256 ]  fp32
// ---------------------------------------------------------------------------

#define BATCH     4
#define CH        256
#define HW        16384
#define HEADS     4
#define DHEAD     64
#define NKEY      256
#define NT_TOTAL  65536
#define OUT_ELEMS (BATCH * CH * HW)

// ---------------- scratch (device globals) ----------------------------------
__device__ float g_y1[BATCH * CH * HW];                 // y2 (attn output, ch layout)
__device__ float g_qkv[BATCH * 3 * CH * HW];            // only K,V regions used now
__device__ __align__(128) __nv_bfloat16 g_a1[768 * 512];   // [Ah|Al]
__device__ __align__(128) __nv_bfloat16 g_a2[256 * 512];
__device__ __align__(128) __nv_bfloat16 g_bT[(size_t)NT_TOTAL * 512]; // [Bh|Bl]
__device__ __align__(128) __nv_bfloat16 g_qTh[(size_t)BATCH * HEADS * HW * DHEAD];
__device__ __align__(128) __nv_bfloat16 g_qTl[(size_t)BATCH * HEADS * HW * DHEAD];
__device__ __align__(128) __nv_bfloat16 g_kTh[16 * NKEY * DHEAD];
__device__ __align__(128) __nv_bfloat16 g_kTl[16 * NKEY * DHEAD];
__device__ __align__(128) __nv_bfloat16 g_vTh[16 * DHEAD * NKEY];  // [d][key]
__device__ __align__(128) __nv_bfloat16 g_vTl[16 * DHEAD * NKEY];
__device__ __align__(128) __nv_bfloat16 g_Rh[64 * 64];   // rows 0-30 relw, 32-62 relh
__device__ __align__(128) __nv_bfloat16 g_Rl[64 * 64];

// ======================= PTX helpers ========================================
__device__ __forceinline__ uint32_t smem_u32(const void* p) {
    uint32_t a;
    asm("{ .reg .u64 t; cvta.to.shared.u64 t, %1; cvt.u32.u64 %0, t; }" : "=r"(a) : "l"(p));
    return a;
}
__device__ __forceinline__ void cp16(uint32_t dst, const void* src) {
    asm volatile("{ .reg .u64 g; cvta.to.global.u64 g, %1; "
                 "cp.async.cg.shared.global [%0], [g], 16; }"
                 :: "r"(dst), "l"(src));
}
__device__ __forceinline__ void ldsm4(uint32_t* r, uint32_t a) {
    asm volatile("ldmatrix.sync.aligned.m8n8.x4.shared.b16 {%0,%1,%2,%3}, [%4];"
                 : "=r"(r[0]), "=r"(r[1]), "=r"(r[2]), "=r"(r[3]) : "r"(a));
}
__device__ __forceinline__ void mma16816(float* c, const uint32_t* a,
                                         uint32_t b0, uint32_t b1) {
    asm volatile("mma.sync.aligned.m16n8k16.row.col.f32.bf16.bf16.f32 "
                 "{%0,%1,%2,%3}, {%4,%5,%6,%7}, {%8,%9}, {%0,%1,%2,%3};"
                 : "+f"(c[0]), "+f"(c[1]), "+f"(c[2]), "+f"(c[3])
                 : "r"(a[0]), "r"(a[1]), "r"(a[2]), "r"(a[3]), "r"(b0), "r"(b1));
}
__device__ __forceinline__ uint32_t packbf(float a, float b) {
    __nv_bfloat162 h = __floats2bfloat162_rn(a, b);
    return *reinterpret_cast<uint32_t*>(&h);
}

// ---------------- weight split fp32 -> bf16 [hi|lo] -------------------------
__global__ __launch_bounds__(256) void convert_w(const float* __restrict__ pw1,
                                                 const float* __restrict__ pw2) {
    int idx = blockIdx.x * 256 + threadIdx.x;
    float f;
    if (idx < 768 * 256) f = pw1[idx]; else f = pw2[idx - 768 * 256];
    __nv_bfloat16 hi = __float2bfloat16_rn(f);
    __nv_bfloat16 lo = __float2bfloat16_rn(f - __bfloat162float(hi));
    if (idx < 768 * 256) {
        int m = idx >> 8, c = idx & 255;
        g_a1[m * 512 + c] = hi; g_a1[m * 512 + 256 + c] = lo;
    } else {
        int r = idx - 768 * 256;
        int m = r >> 8, c = r & 255;
        g_a2[m * 512 + c] = hi; g_a2[m * 512 + 256 + c] = lo;
    }
}

// ---------------- rel table build -------------------------------------------
__global__ __launch_bounds__(256) void rel_build(const float* __restrict__ relw,
                                                 const float* __restrict__ relh) {
    int idx = blockIdx.x * 256 + threadIdx.x;   // 4096
    int row = idx >> 6, d = idx & 63;
    float v = 0.f;
    if (row < 31) v = relw[row * 64 + d];
    else if (row >= 32 && row < 63) v = relh[(row - 32) * 64 + d];
    __nv_bfloat16 hi = __float2bfloat16_rn(v);
    g_Rh[idx] = hi;
    g_Rl[idx] = __float2bfloat16_rn(v - __bfloat162float(hi));
}

// ========== fused depthwise 3x3 + bf16 hi/lo split + transpose ==============
#define DWT_SMEM (16 * 10 * 136 * 4)     // 87040

__global__ __launch_bounds__(256) void dwt(const float* __restrict__ in,
                                           const float* __restrict__ wt) {
    extern __shared__ float sIn[];
    __shared__ float sW[144];
    int t = threadIdx.x;
    int tc = t >> 4, l = t & 15;
    int y0 = blockIdx.x * 8, c0 = blockIdx.y * 16, b = blockIdx.z;

    const float* ip = in + (((size_t)(b * 256 + c0 + tc)) << 14);
#pragma unroll
    for (int r = 0; r < 10; r++) {
        int yy = y0 - 1 + r;
        float4 v0 = make_float4(0.f, 0.f, 0.f, 0.f), v1 = v0;
        if (yy >= 0 && yy < 128) {
            v0 = *reinterpret_cast<const float4*>(ip + (yy << 7) + l * 8);
            v1 = *reinterpret_cast<const float4*>(ip + (yy << 7) + l * 8 + 4);
        }
        float* dst = sIn + (tc * 10 + r) * 136 + 4 + l * 8;
        *reinterpret_cast<float4*>(dst) = v0;
        *reinterpret_cast<float4*>(dst + 4) = v1;
    }
    if (l < 10) {
        sIn[(tc * 10 + l) * 136 + 3] = 0.f;
        sIn[(tc * 10 + l) * 136 + 132] = 0.f;
    }
    if (t < 144) sW[t] = wt[(size_t)c0 * 9 + t];
    __syncthreads();

    size_t nbase = (size_t)b * HW + (size_t)y0 * 128;
#pragma unroll
    for (int i = 0; i < 4; i++) {
        int p = i * 256 + t;
        int x = p & 127, y = p >> 7;
        float o[16];
#pragma unroll
        for (int c = 0; c < 16; c++) {
            const float* base = sIn + (c * 10 + y) * 136 + 3 + x;
            const float* w = sW + c * 9;
            float s = 0.f;
#pragma unroll
            for (int dy = 0; dy < 3; dy++) {
                const float* rp = base + dy * 136;
                s += rp[0] * w[dy * 3] + rp[1] * w[dy * 3 + 1] + rp[2] * w[dy * 3 + 2];
            }
            o[c] = s;
        }
        uint32_t hp[8], lp[8];
#pragma unroll
        for (int q = 0; q < 8; q++) {
            __nv_bfloat16 h0 = __float2bfloat16_rn(o[2 * q]);
            __nv_bfloat16 h1 = __float2bfloat16_rn(o[2 * q + 1]);
            hp[q] = (uint32_t)__bfloat16_as_ushort(h0) |
                    ((uint32_t)__bfloat16_as_ushort(h1) << 16);
            lp[q] = packbf(o[2 * q] - __bfloat162float(h0),
                           o[2 * q + 1] - __bfloat162float(h1));
        }
        __nv_bfloat16* gp = g_bT + (nbase + p) * 512 + c0;
        *reinterpret_cast<uint4*>(gp)           = make_uint4(hp[0], hp[1], hp[2], hp[3]);
        *reinterpret_cast<uint4*>(gp + 8)       = make_uint4(hp[4], hp[5], hp[6], hp[7]);
        *reinterpret_cast<uint4*>(gp + 256)     = make_uint4(lp[0], lp[1], lp[2], lp[3]);
        *reinterpret_cast<uint4*>(gp + 256 + 8) = make_uint4(lp[4], lp[5], lp[6], lp[7]);
    }
}

// ============ HMMA GEMM, 8 stages: phase1 (Ah+Al)·Bh, phase2 Ah·Bl ==========
#define SROW 72
#define GBUF (128 * SROW * 2)            // 18432 B per tile slot
#define GEMM_SMEM (6 * GBUF)             // 110592
#define QROW 136                          // staging row stride (elems), 272 B

template <bool DUAL>
__device__ __forceinline__ void gstage_compute(uint32_t aB, uint32_t bB,
                                               float acc[2][8][4],
                                               int lane, int wm, int wn) {
#pragma unroll
    for (int k16 = 0; k16 < 4; k16++) {
        uint32_t af[2][4], afl[2][4];
#pragma unroll
        for (int mt = 0; mt < 2; mt++) {
            int row = wm * 32 + mt * 16 + (lane & 15);
            int col = k16 * 16 + (lane >> 4) * 8;
            ldsm4(af[mt], aB + (row * SROW + col) * 2);
            if (DUAL) ldsm4(afl[mt], aB + GBUF + (row * SROW + col) * 2);
        }
#pragma unroll
        for (int nq = 0; nq < 4; nq++) {
            uint32_t bfr[4];
            int n = wn * 64 + nq * 16 + ((lane >> 4) << 3) + (lane & 7);
            int kc = k16 * 16 + ((lane >> 3) & 1) * 8;
            ldsm4(bfr, bB + (n * SROW + kc) * 2);
#pragma unroll
            for (int mt = 0; mt < 2; mt++) {
                mma16816(acc[mt][nq * 2],     af[mt], bfr[0], bfr[1]);
                mma16816(acc[mt][nq * 2 + 1], af[mt], bfr[2], bfr[3]);
                if (DUAL) {
                    mma16816(acc[mt][nq * 2],     afl[mt], bfr[0], bfr[1]);
                    mma16816(acc[mt][nq * 2 + 1], afl[mt], bfr[2], bfr[3]);
                }
            }
        }
    }
}

template <bool QEPI>
__device__ __forceinline__ void gemm_mma_body(const __nv_bfloat16* __restrict__ A,
                                              float* __restrict__ C) {
    extern __shared__ char smg[];
    uint32_t sAb = smem_u32(smg);                 // 2 pair-buffers of [Ah|Al]
    uint32_t sBb = sAb + 4 * GBUF;                // 2 B buffers
    int t = threadIdx.x, lane = t & 31, w = t >> 5;
    int wm = w >> 1, wn = w & 1;
    int mtb = blockIdx.x, nt = blockIdx.y;
    int Mrows = gridDim.x * 128;

    const __nv_bfloat16* Ab = A + (size_t)mtb * 128 * 512;
    const __nv_bfloat16* Bb = g_bT + (size_t)nt * 128 * 512;

    float acc[2][8][4];
#pragma unroll
    for (int i = 0; i < 2; i++)
#pragma unroll
        for (int j = 0; j < 8; j++)
#pragma unroll
            for (int q = 0; q < 4; q++) acc[i][j][q] = 0.f;

    auto stage_load = [&](int s, int buf) {
        bool ph1 = (s < 4);
        int k0 = ph1 ? s * 64 : (s - 4) * 64;
        int bo = ph1 ? k0 : 256 + k0;
        uint32_t da = sAb + buf * (2 * GBUF);
        uint32_t db = sBb + buf * GBUF;
#pragma unroll
        for (int i = 0; i < 4; i++) {
            int idx = i * 256 + t;
            int row = idx >> 3, col = (idx & 7) * 8;
            cp16(da + (row * SROW + col) * 2, Ab + (size_t)row * 512 + k0 + col);
            cp16(db + (row * SROW + col) * 2, Bb + (size_t)row * 512 + bo + col);
        }
        if (ph1) {
#pragma unroll
            for (int i = 0; i < 4; i++) {
                int idx = i * 256 + t;
                int row = idx >> 3, col = (idx & 7) * 8;
                cp16(da + GBUF + (row * SROW + col) * 2,
                     Ab + (size_t)row * 512 + 256 + k0 + col);
            }
        }
        asm volatile("cp.async.commit_group;" ::: "memory");
    };

    stage_load(0, 0);
#pragma unroll 1
    for (int s = 0; s < 4; s++) {
        asm volatile("cp.async.wait_group 0;" ::: "memory");
        __syncthreads();
        if (s + 1 < 8) stage_load(s + 1, (s + 1) & 1);
        gstage_compute<true>(sAb + (s & 1) * 2 * GBUF, sBb + (s & 1) * GBUF,
                             acc, lane, wm, wn);
    }
#pragma unroll 1
    for (int s = 4; s < 8; s++) {
        asm volatile("cp.async.wait_group 0;" ::: "memory");
        __syncthreads();
        if (s + 1 < 8) stage_load(s + 1, (s + 1) & 1);
        gstage_compute<false>(sAb + (s & 1) * 2 * GBUF, sBb + (s & 1) * GBUF,
                              acc, lane, wm, wn);
    }

    int b = nt >> 7;
    int n0 = (nt & 127) * 128;

    if (QEPI && mtb < 2) {
        // ---- fused Q epilogue: split + transpose into g_qTh/g_qTl ----
        __nv_bfloat16* sqh = reinterpret_cast<__nv_bfloat16*>(smg);
        __nv_bfloat16* sql = sqh + 128 * QROW;          // 34816 B each
        __syncthreads();   // mainloop smem reads done
#pragma unroll
        for (int mt = 0; mt < 2; mt++) {
            int r0 = wm * 32 + mt * 16 + (lane >> 2);   // local channel
            int r1 = r0 + 8;
            int cc0 = (r0 & 3) * 32 + (r0 >> 2);
            int cc1 = (r1 & 3) * 32 + (r1 >> 2);
#pragma unroll
            for (int nq = 0; nq < 8; nq++) {
                int col = wn * 64 + nq * 8 + (lane & 3) * 2;
                float a0 = acc[mt][nq][0], a1 = acc[mt][nq][1];
                float a2 = acc[mt][nq][2], a3 = acc[mt][nq][3];
                __nv_bfloat16 h0 = __float2bfloat16_rn(a0);
                __nv_bfloat16 h1 = __float2bfloat16_rn(a1);
                __nv_bfloat16 h2 = __float2bfloat16_rn(a2);
                __nv_bfloat16 h3 = __float2bfloat16_rn(a3);
                sqh[col * QROW + cc0]       = h0;
                sqh[(col + 1) * QROW + cc0] = h1;
                sqh[col * QROW + cc1]       = h2;
                sqh[(col + 1) * QROW + cc1] = h3;
                sql[col * QROW + cc0]       = __float2bfloat16_rn(a0 - __bfloat162float(h0));
                sql[(col + 1) * QROW + cc0] = __float2bfloat16_rn(a1 - __bfloat162float(h1));
                sql[col * QROW + cc1]       = __float2bfloat16_rn(a2 - __bfloat162float(h2));
                sql[(col + 1) * QROW + cc1] = __float2bfloat16_rn(a3 - __bfloat162float(h3));
            }
        }
        __syncthreads();
        // store: chunk = (head, pos) -> 32 d-contiguous bf16 = 64 B
        int pos = t & 127;
#pragma unroll
        for (int it = 0; it < 2; it++) {
            int head = (t >> 7) + it * 2;
            const uint4* sh = reinterpret_cast<const uint4*>(sqh + pos * QROW + head * 32);
            const uint4* sl = reinterpret_cast<const uint4*>(sql + pos * QROW + head * 32);
            size_t base = ((((size_t)(b * HEADS + head)) << 14) + n0 + pos) * 64 + mtb * 32;
            uint4* dh = reinterpret_cast<uint4*>(g_qTh + base);
            uint4* dl = reinterpret_cast<uint4*>(g_qTl + base);
#pragma unroll
            for (int u = 0; u < 4; u++) { dh[u] = sh[u]; dl[u] = sl[u]; }
        }
        return;
    }

    size_t base = (size_t)b * Mrows * HW + (size_t)mtb * 128 * HW + n0;
#pragma unroll
    for (int mt = 0; mt < 2; mt++) {
        int row0 = wm * 32 + mt * 16 + (lane >> 2);
#pragma unroll
        for (int nq = 0; nq < 8; nq++) {
            int col = wn * 64 + nq * 8 + (lane & 3) * 2;
            *reinterpret_cast<float2*>(&C[base + (size_t)row0 * HW + col]) =
                make_float2(acc[mt][nq][0], acc[mt][nq][1]);
            *reinterpret_cast<float2*>(&C[base + (size_t)(row0 + 8) * HW + col]) =
                make_float2(acc[mt][nq][2], acc[mt][nq][3]);
        }
    }
}
__global__ __launch_bounds__(256) void gemm_mma_pw1() { gemm_mma_body<true>(g_a1, g_qkv); }
__global__ __launch_bounds__(256) void gemm_mma_pw2(float* __restrict__ out) {
    gemm_mma_body<false>(g_a2, out);
}

// ---------------- 8x8 max pool k,v -> bf16 split ----------------------------
__global__ __launch_bounds__(256) void pool_kv() {
    int idx = blockIdx.x * 256 + threadIdx.x;
    int wk = idx & 15;
    int hk = (idx >> 4) & 15;
    int c = (idx >> 8) & 255;
    int which = (idx >> 16) & 1;
    int b = idx >> 17;
    int ch = 256 + which * 256 + c;
    const float* src = g_qkv + (((size_t)(b * 768 + ch)) << 14) + ((hk * 8) << 7) + wk * 8;
    float m = -3.402823466e+38f;
#pragma unroll
    for (int dy = 0; dy < 8; dy++)
#pragma unroll
        for (int dx = 0; dx < 8; dx++)
            m = fmaxf(m, src[(dy << 7) + dx]);
    int head = c & 3, d = c >> 2;
    int bh = b * HEADS + head, key = hk * 16 + wk;
    __nv_bfloat16 hi = __float2bfloat16_rn(m);
    __nv_bfloat16 lo = __float2bfloat16_rn(m - __bfloat162float(hi));
    if (which == 0) {
        g_kTh[(bh * NKEY + key) * DHEAD + d] = hi;
        g_kTl[(bh * NKEY + key) * DHEAD + d] = lo;
    } else {
        g_vTh[(bh * DHEAD + d) * NKEY + key] = hi;
        g_vTl[(bh * DHEAD + d) * NKEY + key] = lo;
    }
}

// ================= HMMA attention (256 threads) =============================
#define AT_KH   0
#define AT_KL   36864
#define AT_VH   0
#define AT_VL   33792
#define AT_QH   73728
#define AT_QL   92160
#define AT_RH   110592
#define AT_RL   119808
#define AT_LWH  129024
#define AT_PM   162816
#define AT_PS   163840
#define AT_SMEM 164864

__global__ __launch_bounds__(256, 1) void attn_kernel(float* __restrict__ attn_out) {
    extern __shared__ char smc[];
    uint32_t sb = smem_u32(smc);
    int t = threadIdx.x, lane = t & 31, w = t >> 5;
    int wm = w >> 1, wn = w & 1;
    int hq = blockIdx.x, head = blockIdx.y, b = blockIdx.z;
    int bh = b * HEADS + head;
    int hq8 = hq >> 3;

    const __nv_bfloat16* kh = g_kTh + (size_t)bh * NKEY * DHEAD;
    const __nv_bfloat16* kl = g_kTl + (size_t)bh * NKEY * DHEAD;
    const __nv_bfloat16* qh = g_qTh + (((size_t)bh << 14) + (size_t)hq * 128) * 64;
    const __nv_bfloat16* ql = g_qTl + (((size_t)bh << 14) + (size_t)hq * 128) * 64;
#pragma unroll
    for (int i = 0; i < 8; i++) {
        int idx = i * 256 + t, row = idx >> 3, col = (idx & 7) * 8;
        cp16(sb + AT_KH + (row * 72 + col) * 2, kh + row * 64 + col);
        cp16(sb + AT_KL + (row * 72 + col) * 2, kl + row * 64 + col);
    }
#pragma unroll
    for (int i = 0; i < 4; i++) {
        int idx = i * 256 + t, row = idx >> 3, col = (idx & 7) * 8;
        cp16(sb + AT_QH + (row * 72 + col) * 2, qh + row * 64 + col);
        cp16(sb + AT_QL + (row * 72 + col) * 2, ql + row * 64 + col);
    }
#pragma unroll
    for (int i = 0; i < 2; i++) {
        int idx = i * 256 + t, row = idx >> 3, col = (idx & 7) * 8;
        cp16(sb + AT_RH + (row * 72 + col) * 2, g_Rh + row * 64 + col);
        cp16(sb + AT_RL + (row * 72 + col) * 2, g_Rl + row * 64 + col);
    }
    asm volatile("cp.async.commit_group;" ::: "memory");
    asm volatile("cp.async.wait_group 0;" ::: "memory");
    __syncthreads();

    uint32_t qsrc[3] = { sb + AT_QH, sb + AT_QL, sb + AT_QH };

    {
        float rc[2][4][4];
#pragma unroll
        for (int i = 0; i < 2; i++)
#pragma unroll
            for (int j = 0; j < 4; j++)
#pragma unroll
                for (int q = 0; q < 4; q++) rc[i][j][q] = 0.f;
        uint32_t rsrc[3] = { sb + AT_RH, sb + AT_RH, sb + AT_RL };
#pragma unroll
        for (int term = 0; term < 3; term++)
#pragma unroll
            for (int k16 = 0; k16 < 4; k16++) {
                uint32_t af[2][4];
#pragma unroll
                for (int mt = 0; mt < 2; mt++) {
                    int row = wm * 32 + mt * 16 + (lane & 15);
                    int col = k16 * 16 + (lane >> 4) * 8;
                    ldsm4(af[mt], qsrc[term] + (row * 72 + col) * 2);
                }
#pragma unroll
                for (int nq = 0; nq < 2; nq++) {
                    uint32_t bfr[4];
                    int n = wn * 32 + nq * 16 + ((lane >> 4) << 3) + (lane & 7);
                    int kc = k16 * 16 + ((lane >> 3) & 1) * 8;
                    ldsm4(bfr, rsrc[term] + (n * 72 + kc) * 2);
#pragma unroll
                    for (int mt = 0; mt < 2; mt++) {
                        mma16816(rc[mt][nq * 2],     af[mt], bfr[0], bfr[1]);
                        mma16816(rc[mt][nq * 2 + 1], af[mt], bfr[2], bfr[3]);
                    }
                }
            }
        float* LWH = reinterpret_cast<float*>(smc + AT_LWH);
#pragma unroll
        for (int mt = 0; mt < 2; mt++) {
            int r0 = wm * 32 + mt * 16 + (lane >> 2);
#pragma unroll
            for (int nf = 0; nf < 4; nf++) {
                int c = wn * 32 + nf * 8 + (lane & 3) * 2;
                LWH[r0 * 66 + c]       = rc[mt][nf][0];
                LWH[r0 * 66 + c + 1]   = rc[mt][nf][1];
                LWH[(r0 + 8) * 66 + c]     = rc[mt][nf][2];
                LWH[(r0 + 8) * 66 + c + 1] = rc[mt][nf][3];
            }
        }
    }
    __syncthreads();

    float acc[2][16][4];
#pragma unroll
    for (int i = 0; i < 2; i++)
#pragma unroll
        for (int j = 0; j < 16; j++)
#pragma unroll
            for (int q = 0; q < 4; q++) acc[i][j][q] = 0.f;
    {
        uint32_t ksrc[3] = { sb + AT_KH, sb + AT_KH, sb + AT_KL };
#pragma unroll
        for (int term = 0; term < 3; term++)
#pragma unroll
            for (int k16 = 0; k16 < 4; k16++) {
                uint32_t af[2][4];
#pragma unroll
                for (int mt = 0; mt < 2; mt++) {
                    int row = wm * 32 + mt * 16 + (lane & 15);
                    int col = k16 * 16 + (lane >> 4) * 8;
                    ldsm4(af[mt], qsrc[term] + (row * 72 + col) * 2);
                }
#pragma unroll
                for (int nq = 0; nq < 8; nq++) {
                    uint32_t bfr[4];
                    int n = wn * 128 + nq * 16 + ((lane >> 4) << 3) + (lane & 7);
                    int kc = k16 * 16 + ((lane >> 3) & 1) * 8;
                    ldsm4(bfr, ksrc[term] + (n * 72 + kc) * 2);
#pragma unroll
                    for (int mt = 0; mt < 2; mt++) {
                        mma16816(acc[mt][nq * 2],     af[mt], bfr[0], bfr[1]);
                        mma16816(acc[mt][nq * 2 + 1], af[mt], bfr[2], bfr[3]);
                    }
                }
            }
    }
    __syncthreads();

    {
        const __nv_bfloat16* vh = g_vTh + (size_t)bh * DHEAD * NKEY;
        const __nv_bfloat16* vl = g_vTl + (size_t)bh * DHEAD * NKEY;
#pragma unroll
        for (int i = 0; i < 8; i++) {
            int idx = i * 256 + t, row = idx >> 5, col = (idx & 31) * 8;
            cp16(sb + AT_VH + (row * 264 + col) * 2, vh + row * 256 + col);
            cp16(sb + AT_VL + (row * 264 + col) * 2, vl + row * 256 + col);
        }
        asm volatile("cp.async.commit_group;" ::: "memory");
    }

    float* LWH = reinterpret_cast<float*>(smc + AT_LWH);
    float* pm = reinterpret_cast<float*>(smc + AT_PM);
    float* ps = reinterpret_cast<float*>(smc + AT_PS);
    int r0t[2], r1t[2];
    float mx[2][2];
#pragma unroll
    for (int mt = 0; mt < 2; mt++) {
        r0t[mt] = wm * 32 + mt * 16 + (lane >> 2);
        r1t[mt] = r0t[mt] + 8;
        mx[mt][0] = -3.402823466e+38f; mx[mt][1] = -3.402823466e+38f;
        int wq80 = r0t[mt] >> 3, wq81 = r1t[mt] >> 3;
        const float* L0 = &LWH[r0t[mt] * 66];
        const float* L1 = &LWH[r1t[mt] * 66];
#pragma unroll
        for (int nf = 0; nf < 16; nf++) {
            int j = wn * 16 + nf;
            int hk = j >> 1;
            int c0 = (j & 1) * 8 + (lane & 3) * 2;
            float bh0 = L0[32 + hk - hq8 + 15];
            float bh1 = L1[32 + hk - hq8 + 15];
            float v0 = (acc[mt][nf][0] + bh0 + L0[c0 - wq80 + 15])     * 0.125f;
            float v1 = (acc[mt][nf][1] + bh0 + L0[c0 + 1 - wq80 + 15]) * 0.125f;
            float v2 = (acc[mt][nf][2] + bh1 + L1[c0 - wq81 + 15])     * 0.125f;
            float v3 = (acc[mt][nf][3] + bh1 + L1[c0 + 1 - wq81 + 15]) * 0.125f;
            acc[mt][nf][0] = v0; acc[mt][nf][1] = v1;
            acc[mt][nf][2] = v2; acc[mt][nf][3] = v3;
            mx[mt][0] = fmaxf(mx[mt][0], fmaxf(v0, v1));
            mx[mt][1] = fmaxf(mx[mt][1], fmaxf(v2, v3));
        }
#pragma unroll
        for (int o = 1; o <= 2; o <<= 1) {
            mx[mt][0] = fmaxf(mx[mt][0], __shfl_xor_sync(0xffffffffu, mx[mt][0], o));
            mx[mt][1] = fmaxf(mx[mt][1], __shfl_xor_sync(0xffffffffu, mx[mt][1], o));
        }
        pm[r0t[mt] * 2 + wn] = mx[mt][0];
        pm[r1t[mt] * 2 + wn] = mx[mt][1];
    }
    __syncthreads();
    float sum[2][2];
#pragma unroll
    for (int mt = 0; mt < 2; mt++) {
        float M0 = fmaxf(pm[r0t[mt] * 2], pm[r0t[mt] * 2 + 1]);
        float M1 = fmaxf(pm[r1t[mt] * 2], pm[r1t[mt] * 2 + 1]);
        sum[mt][0] = 0.f; sum[mt][1] = 0.f;
#pragma unroll
        for (int nf = 0; nf < 16; nf++) {
            float e0 = __expf(acc[mt][nf][0] - M0);
            float e1 = __expf(acc[mt][nf][1] - M0);
            float e2 = __expf(acc[mt][nf][2] - M1);
            float e3 = __expf(acc[mt][nf][3] - M1);
            acc[mt][nf][0] = e0; acc[mt][nf][1] = e1;
            acc[mt][nf][2] = e2; acc[mt][nf][3] = e3;
            sum[mt][0] += e0 + e1; sum[mt][1] += e2 + e3;
        }
#pragma unroll
        for (int o = 1; o <= 2; o <<= 1) {
            sum[mt][0] += __shfl_xor_sync(0xffffffffu, sum[mt][0], o);
            sum[mt][1] += __shfl_xor_sync(0xffffffffu, sum[mt][1], o);
        }
        ps[r0t[mt] * 2 + wn] = sum[mt][0];
        ps[r1t[mt] * 2 + wn] = sum[mt][1];
    }
    __syncthreads();

    size_t abase = ((size_t)bh * HW + (size_t)hq * 128) * NKEY;
    uint32_t uh[2][16], vh_[2][16], ul[2][16];
    uint32_t* vlS = reinterpret_cast<uint32_t*>(smc + AT_LWH) + t * 32;
#pragma unroll
    for (int mt = 0; mt < 2; mt++) {
        float inv0 = 1.f / (ps[r0t[mt] * 2] + ps[r0t[mt] * 2 + 1]);
        float inv1 = 1.f / (ps[r1t[mt] * 2] + ps[r1t[mt] * 2 + 1]);
#pragma unroll
        for (int nf = 0; nf < 16; nf++) {
            int j = wn * 16 + nf;
            int col = j * 8 + (lane & 3) * 2;
            float p0 = acc[mt][nf][0] * inv0, p1 = acc[mt][nf][1] * inv0;
            float p2 = acc[mt][nf][2] * inv1, p3 = acc[mt][nf][3] * inv1;
            __stcs(reinterpret_cast<float2*>(&attn_out[abase + (size_t)r0t[mt] * 256 + col]),
                   make_float2(p0, p1));
            __stcs(reinterpret_cast<float2*>(&attn_out[abase + (size_t)r1t[mt] * 256 + col]),
                   make_float2(p2, p3));
            uint32_t h01 = packbf(p0, p1), h23 = packbf(p2, p3);
            uh[mt][nf] = h01; vh_[mt][nf] = h23;
            __nv_bfloat162 hh01 = *reinterpret_cast<__nv_bfloat162*>(&h01);
            __nv_bfloat162 hh23 = *reinterpret_cast<__nv_bfloat162*>(&h23);
            ul[mt][nf] = packbf(p0 - __bfloat162float(hh01.x), p1 - __bfloat162float(hh01.y));
            vlS[mt * 16 + nf] = packbf(p2 - __bfloat162float(hh23.x), p3 - __bfloat162float(hh23.y));
        }
    }

    asm volatile("cp.async.wait_group 0;" ::: "memory");
    __syncthreads();
    float oacc[2][8][4];
#pragma unroll
    for (int i = 0; i < 2; i++)
#pragma unroll
        for (int j = 0; j < 8; j++)
#pragma unroll
            for (int q = 0; q < 4; q++) oacc[i][j][q] = 0.f;
#pragma unroll
    for (int kk = 0; kk < 8; kk++) {
        uint32_t afh[2][4], afl[2][4];
#pragma unroll
        for (int mt = 0; mt < 2; mt++) {
            afh[mt][0] = uh[mt][2 * kk];     afh[mt][1] = vh_[mt][2 * kk];
            afh[mt][2] = uh[mt][2 * kk + 1]; afh[mt][3] = vh_[mt][2 * kk + 1];
            afl[mt][0] = ul[mt][2 * kk];     afl[mt][1] = vlS[mt * 16 + 2 * kk];
            afl[mt][2] = ul[mt][2 * kk + 1]; afl[mt][3] = vlS[mt * 16 + 2 * kk + 1];
        }
        int kc = wn * 128 + kk * 16 + ((lane >> 3) & 1) * 8;
#pragma unroll
        for (int nq = 0; nq < 4; nq++) {
            int n = nq * 16 + ((lane >> 4) << 3) + (lane & 7);
            uint32_t bh_[4], bl_[4];
            ldsm4(bh_, sb + AT_VH + (n * 264 + kc) * 2);
            ldsm4(bl_, sb + AT_VL + (n * 264 + kc) * 2);
#pragma unroll
            for (int mt = 0; mt < 2; mt++) {
                mma16816(oacc[mt][nq * 2],     afh[mt], bh_[0], bh_[1]);
                mma16816(oacc[mt][nq * 2 + 1], afh[mt], bh_[2], bh_[3]);
                mma16816(oacc[mt][nq * 2],     afl[mt], bh_[0], bh_[1]);
                mma16816(oacc[mt][nq * 2 + 1], afl[mt], bh_[2], bh_[3]);
                mma16816(oacc[mt][nq * 2],     afh[mt], bl_[0], bl_[1]);
                mma16816(oacc[mt][nq * 2 + 1], afh[mt], bl_[2], bl_[3]);
            }
        }
    }

    float* oT = reinterpret_cast<float*>(smc + AT_LWH);   // [64][129]
    __syncthreads();
    if (wn == 0) {
#pragma unroll
        for (int mt = 0; mt < 2; mt++)
#pragma unroll
            for (int nf = 0; nf < 8; nf++) {
                int d = nf * 8 + (lane & 3) * 2;
                oT[d * 129 + r0t[mt]]       = oacc[mt][nf][0];
                oT[(d + 1) * 129 + r0t[mt]] = oacc[mt][nf][1];
                oT[d * 129 + r1t[mt]]       = oacc[mt][nf][2];
                oT[(d + 1) * 129 + r1t[mt]] = oacc[mt][nf][3];
            }
    }
    __syncthreads();
    if (wn == 1) {
#pragma unroll
        for (int mt = 0; mt < 2; mt++)
#pragma unroll
            for (int nf = 0; nf < 8; nf++) {
                int d = nf * 8 + (lane & 3) * 2;
                oT[d * 129 + r0t[mt]]       += oacc[mt][nf][0];
                oT[(d + 1) * 129 + r0t[mt]] += oacc[mt][nf][1];
                oT[d * 129 + r1t[mt]]       += oacc[mt][nf][2];
                oT[(d + 1) * 129 + r1t[mt]] += oacc[mt][nf][3];
            }
    }
    __syncthreads();
    for (int i = t; i < 64 * 128; i += 256) {
        int d = i >> 7, x = i & 127;
        g_y1[(((size_t)(b * CH + d * 4 + head)) * 128 + hq) * 128 + x] = oT[d * 129 + x];
    }
}

// ---------------------------------------------------------------------------
extern "C" void kernel_launch(void* const* d_in, const int* in_sizes, int n_in,
                              void* d_out, int out_size) {
    (void)in_sizes; (void)n_in; (void)out_size;
    const float* x    = (const float*)d_in[0];
    const float* dw1  = (const float*)d_in[1];
    const float* pw1  = (const float*)d_in[2];
    const float* relw = (const float*)d_in[3];
    const float* relh = (const float*)d_in[4];
    const float* dw2  = (const float*)d_in[5];
    const float* pw2  = (const float*)d_in[6];
    float* out  = (float*)d_out;
    float* attn = out + OUT_ELEMS;

    float* y2;
    cudaGetSymbolAddress((void**)&y2, g_y1);

    cudaFuncSetAttribute(attn_kernel, cudaFuncAttributeMaxDynamicSharedMemorySize, AT_SMEM);
    cudaFuncSetAttribute(gemm_mma_pw1, cudaFuncAttributeMaxDynamicSharedMemorySize, GEMM_SMEM);
    cudaFuncSetAttribute(gemm_mma_pw2, cudaFuncAttributeMaxDynamicSharedMemorySize, GEMM_SMEM);
    cudaFuncSetAttribute(dwt, cudaFuncAttributeMaxDynamicSharedMemorySize, DWT_SMEM);

    convert_w<<<1024, 256>>>(pw1, pw2);
    rel_build<<<16, 256>>>(relw, relh);
    dwt<<<dim3(16, 16, 4), 256, DWT_SMEM>>>(x, dw1);
    gemm_mma_pw1<<<dim3(6, 512), 256, GEMM_SMEM>>>();
    pool_kv<<<2048, 256>>>();
    attn_kernel<<<dim3(128, HEADS, BATCH), 256, AT_SMEM>>>(attn);
    dwt<<<dim3(16, 16, 4), 256, DWT_SMEM>>>(y2, dw2);
    gemm_mma_pw2<<<dim3(2, 512), 256, GEMM_SMEM>>>(out);
}

// round 14
// speedup vs baseline: 1.5370x; 1.5370x over previous
#include <cuda_runtime.h>
#include <cuda_bf16.h>
#include <cstdint>
#include <cstddef>

// ---------------------------------------------------------------------------
// SemRelAttention, HMMA everywhere (R12 baseline + fused rel/QK A-frags):
//   convert_w / rel_build : weights + rel tables -> bf16 hi/lo
//   dwt(x,dw1)            : fused dw3x3 + bf16 split + transpose -> g_bT
//   gemm_mma pw1 : 8-stage split (phase1 AhBh+AlBh sharing Bh, phase2 AhBl)
//   pool_kv / transpose_q : bf16 split K,V,Q
//   attn (256 thr, fused rel+QK mma, softmax, AV mma) -> attn region + y2
//   dwt(y2,dw2) -> g_bT ; gemm_mma pw2 -> out region
// d_out = [ out : 4*256*128*128 | attn : 4*4*16384*256 ]  fp32
// ---------------------------------------------------------------------------

#define BATCH     4
#define CH        256
#define HW        16384
#define HEADS     4
#define DHEAD     64
#define NKEY      256
#define NT_TOTAL  65536
#define OUT_ELEMS (BATCH * CH * HW)

// ---------------- scratch (device globals) ----------------------------------
__device__ float g_y1[BATCH * CH * HW];                 // y2 (attn output, ch layout)
__device__ float g_qkv[BATCH * 3 * CH * HW];
__device__ __align__(128) __nv_bfloat16 g_a1[768 * 512];   // [Ah|Al]
__device__ __align__(128) __nv_bfloat16 g_a2[256 * 512];
__device__ __align__(128) __nv_bfloat16 g_bT[(size_t)NT_TOTAL * 512]; // [Bh|Bl]
__device__ __align__(128) __nv_bfloat16 g_qTh[(size_t)BATCH * HEADS * HW * DHEAD];
__device__ __align__(128) __nv_bfloat16 g_qTl[(size_t)BATCH * HEADS * HW * DHEAD];
__device__ __align__(128) __nv_bfloat16 g_kTh[16 * NKEY * DHEAD];
__device__ __align__(128) __nv_bfloat16 g_kTl[16 * NKEY * DHEAD];
__device__ __align__(128) __nv_bfloat16 g_vTh[16 * DHEAD * NKEY];  // [d][key]
__device__ __align__(128) __nv_bfloat16 g_vTl[16 * DHEAD * NKEY];
__device__ __align__(128) __nv_bfloat16 g_Rh[64 * 64];   // rows 0-30 relw, 32-62 relh
__device__ __align__(128) __nv_bfloat16 g_Rl[64 * 64];

// ======================= PTX helpers ========================================
__device__ __forceinline__ uint32_t smem_u32(const void* p) {
    uint32_t a;
    asm("{ .reg .u64 t; cvta.to.shared.u64 t, %1; cvt.u32.u64 %0, t; }" : "=r"(a) : "l"(p));
    return a;
}
__device__ __forceinline__ void cp16(uint32_t dst, const void* src) {
    asm volatile("{ .reg .u64 g; cvta.to.global.u64 g, %1; "
                 "cp.async.cg.shared.global [%0], [g], 16; }"
                 :: "r"(dst), "l"(src));
}
__device__ __forceinline__ void ldsm4(uint32_t* r, uint32_t a) {
    asm volatile("ldmatrix.sync.aligned.m8n8.x4.shared.b16 {%0,%1,%2,%3}, [%4];"
                 : "=r"(r[0]), "=r"(r[1]), "=r"(r[2]), "=r"(r[3]) : "r"(a));
}
__device__ __forceinline__ void mma16816(float* c, const uint32_t* a,
                                         uint32_t b0, uint32_t b1) {
    asm volatile("mma.sync.aligned.m16n8k16.row.col.f32.bf16.bf16.f32 "
                 "{%0,%1,%2,%3}, {%4,%5,%6,%7}, {%8,%9}, {%0,%1,%2,%3};"
                 : "+f"(c[0]), "+f"(c[1]), "+f"(c[2]), "+f"(c[3])
                 : "r"(a[0]), "r"(a[1]), "r"(a[2]), "r"(a[3]), "r"(b0), "r"(b1));
}
__device__ __forceinline__ uint32_t packbf(float a, float b) {
    __nv_bfloat162 h = __floats2bfloat162_rn(a, b);
    return *reinterpret_cast<uint32_t*>(&h);
}

// ---------------- weight split fp32 -> bf16 [hi|lo] -------------------------
__global__ __launch_bounds__(256) void convert_w(const float* __restrict__ pw1,
                                                 const float* __restrict__ pw2) {
    int idx = blockIdx.x * 256 + threadIdx.x;
    float f;
    if (idx < 768 * 256) f = pw1[idx]; else f = pw2[idx - 768 * 256];
    __nv_bfloat16 hi = __float2bfloat16_rn(f);
    __nv_bfloat16 lo = __float2bfloat16_rn(f - __bfloat162float(hi));
    if (idx < 768 * 256) {
        int m = idx >> 8, c = idx & 255;
        g_a1[m * 512 + c] = hi; g_a1[m * 512 + 256 + c] = lo;
    } else {
        int r = idx - 768 * 256;
        int m = r >> 8, c = r & 255;
        g_a2[m * 512 + c] = hi; g_a2[m * 512 + 256 + c] = lo;
    }
}

// ---------------- rel table build -------------------------------------------
__global__ __launch_bounds__(256) void rel_build(const float* __restrict__ relw,
                                                 const float* __restrict__ relh) {
    int idx = blockIdx.x * 256 + threadIdx.x;   // 4096
    int row = idx >> 6, d = idx & 63;
    float v = 0.f;
    if (row < 31) v = relw[row * 64 + d];
    else if (row >= 32 && row < 63) v = relh[(row - 32) * 64 + d];
    __nv_bfloat16 hi = __float2bfloat16_rn(v);
    g_Rh[idx] = hi;
    g_Rl[idx] = __float2bfloat16_rn(v - __bfloat162float(hi));
}

// ========== fused depthwise 3x3 + bf16 hi/lo split + transpose ==============
#define DWT_SMEM (16 * 10 * 136 * 4)     // 87040

__global__ __launch_bounds__(256) void dwt(const float* __restrict__ in,
                                           const float* __restrict__ wt) {
    extern __shared__ float sIn[];
    __shared__ float sW[144];
    int t = threadIdx.x;
    int tc = t >> 4, l = t & 15;
    int y0 = blockIdx.x * 8, c0 = blockIdx.y * 16, b = blockIdx.z;

    const float* ip = in + (((size_t)(b * 256 + c0 + tc)) << 14);
#pragma unroll
    for (int r = 0; r < 10; r++) {
        int yy = y0 - 1 + r;
        float4 v0 = make_float4(0.f, 0.f, 0.f, 0.f), v1 = v0;
        if (yy >= 0 && yy < 128) {
            v0 = *reinterpret_cast<const float4*>(ip + (yy << 7) + l * 8);
            v1 = *reinterpret_cast<const float4*>(ip + (yy << 7) + l * 8 + 4);
        }
        float* dst = sIn + (tc * 10 + r) * 136 + 4 + l * 8;
        *reinterpret_cast<float4*>(dst) = v0;
        *reinterpret_cast<float4*>(dst + 4) = v1;
    }
    if (l < 10) {
        sIn[(tc * 10 + l) * 136 + 3] = 0.f;
        sIn[(tc * 10 + l) * 136 + 132] = 0.f;
    }
    if (t < 144) sW[t] = wt[(size_t)c0 * 9 + t];
    __syncthreads();

    size_t nbase = (size_t)b * HW + (size_t)y0 * 128;
#pragma unroll
    for (int i = 0; i < 4; i++) {
        int p = i * 256 + t;
        int x = p & 127, y = p >> 7;
        float o[16];
#pragma unroll
        for (int c = 0; c < 16; c++) {
            const float* base = sIn + (c * 10 + y) * 136 + 3 + x;
            const float* w = sW + c * 9;
            float s = 0.f;
#pragma unroll
            for (int dy = 0; dy < 3; dy++) {
                const float* rp = base + dy * 136;
                s += rp[0] * w[dy * 3] + rp[1] * w[dy * 3 + 1] + rp[2] * w[dy * 3 + 2];
            }
            o[c] = s;
        }
        uint32_t hp[8], lp[8];
#pragma unroll
        for (int q = 0; q < 8; q++) {
            __nv_bfloat16 h0 = __float2bfloat16_rn(o[2 * q]);
            __nv_bfloat16 h1 = __float2bfloat16_rn(o[2 * q + 1]);
            hp[q] = (uint32_t)__bfloat16_as_ushort(h0) |
                    ((uint32_t)__bfloat16_as_ushort(h1) << 16);
            lp[q] = packbf(o[2 * q] - __bfloat162float(h0),
                           o[2 * q + 1] - __bfloat162float(h1));
        }
        __nv_bfloat16* gp = g_bT + (nbase + p) * 512 + c0;
        *reinterpret_cast<uint4*>(gp)           = make_uint4(hp[0], hp[1], hp[2], hp[3]);
        *reinterpret_cast<uint4*>(gp + 8)       = make_uint4(hp[4], hp[5], hp[6], hp[7]);
        *reinterpret_cast<uint4*>(gp + 256)     = make_uint4(lp[0], lp[1], lp[2], lp[3]);
        *reinterpret_cast<uint4*>(gp + 256 + 8) = make_uint4(lp[4], lp[5], lp[6], lp[7]);
    }
}

// ============ HMMA GEMM, 8 stages: phase1 (Ah+Al)·Bh, phase2 Ah·Bl ==========
#define SROW 72
#define GBUF (128 * SROW * 2)            // 18432 B per tile slot
#define GEMM_SMEM (6 * GBUF)             // 110592

template <bool DUAL>
__device__ __forceinline__ void gstage_compute(uint32_t aB, uint32_t bB,
                                               float acc[2][8][4],
                                               int lane, int wm, int wn) {
#pragma unroll
    for (int k16 = 0; k16 < 4; k16++) {
        uint32_t af[2][4], afl[2][4];
#pragma unroll
        for (int mt = 0; mt < 2; mt++) {
            int row = wm * 32 + mt * 16 + (lane & 15);
            int col = k16 * 16 + (lane >> 4) * 8;
            ldsm4(af[mt], aB + (row * SROW + col) * 2);
            if (DUAL) ldsm4(afl[mt], aB + GBUF + (row * SROW + col) * 2);
        }
#pragma unroll
        for (int nq = 0; nq < 4; nq++) {
            uint32_t bfr[4];
            int n = wn * 64 + nq * 16 + ((lane >> 4) << 3) + (lane & 7);
            int kc = k16 * 16 + ((lane >> 3) & 1) * 8;
            ldsm4(bfr, bB + (n * SROW + kc) * 2);
#pragma unroll
            for (int mt = 0; mt < 2; mt++) {
                mma16816(acc[mt][nq * 2],     af[mt], bfr[0], bfr[1]);
                mma16816(acc[mt][nq * 2 + 1], af[mt], bfr[2], bfr[3]);
                if (DUAL) {
                    mma16816(acc[mt][nq * 2],     afl[mt], bfr[0], bfr[1]);
                    mma16816(acc[mt][nq * 2 + 1], afl[mt], bfr[2], bfr[3]);
                }
            }
        }
    }
}

__device__ __forceinline__ void gemm_mma_body(const __nv_bfloat16* __restrict__ A,
                                              float* __restrict__ C) {
    extern __shared__ char smg[];
    uint32_t sAb = smem_u32(smg);                 // 2 pair-buffers of [Ah|Al]
    uint32_t sBb = sAb + 4 * GBUF;                // 2 B buffers
    int t = threadIdx.x, lane = t & 31, w = t >> 5;
    int wm = w >> 1, wn = w & 1;
    int mtb = blockIdx.x, nt = blockIdx.y;
    int Mrows = gridDim.x * 128;

    const __nv_bfloat16* Ab = A + (size_t)mtb * 128 * 512;
    const __nv_bfloat16* Bb = g_bT + (size_t)nt * 128 * 512;

    float acc[2][8][4];
#pragma unroll
    for (int i = 0; i < 2; i++)
#pragma unroll
        for (int j = 0; j < 8; j++)
#pragma unroll
            for (int q = 0; q < 4; q++) acc[i][j][q] = 0.f;

    auto stage_load = [&](int s, int buf) {
        bool ph1 = (s < 4);
        int k0 = ph1 ? s * 64 : (s - 4) * 64;
        int bo = ph1 ? k0 : 256 + k0;
        uint32_t da = sAb + buf * (2 * GBUF);
        uint32_t db = sBb + buf * GBUF;
#pragma unroll
        for (int i = 0; i < 4; i++) {
            int idx = i * 256 + t;
            int row = idx >> 3, col = (idx & 7) * 8;
            cp16(da + (row * SROW + col) * 2, Ab + (size_t)row * 512 + k0 + col);
            cp16(db + (row * SROW + col) * 2, Bb + (size_t)row * 512 + bo + col);
        }
        if (ph1) {
#pragma unroll
            for (int i = 0; i < 4; i++) {
                int idx = i * 256 + t;
                int row = idx >> 3, col = (idx & 7) * 8;
                cp16(da + GBUF + (row * SROW + col) * 2,
                     Ab + (size_t)row * 512 + 256 + k0 + col);
            }
        }
        asm volatile("cp.async.commit_group;" ::: "memory");
    };

    stage_load(0, 0);
#pragma unroll 1
    for (int s = 0; s < 4; s++) {
        asm volatile("cp.async.wait_group 0;" ::: "memory");
        __syncthreads();
        if (s + 1 < 8) stage_load(s + 1, (s + 1) & 1);
        gstage_compute<true>(sAb + (s & 1) * 2 * GBUF, sBb + (s & 1) * GBUF,
                             acc, lane, wm, wn);
    }
#pragma unroll 1
    for (int s = 4; s < 8; s++) {
        asm volatile("cp.async.wait_group 0;" ::: "memory");
        __syncthreads();
        if (s + 1 < 8) stage_load(s + 1, (s + 1) & 1);
        gstage_compute<false>(sAb + (s & 1) * 2 * GBUF, sBb + (s & 1) * GBUF,
                              acc, lane, wm, wn);
    }

    int b = nt >> 7;
    int n0 = (nt & 127) * 128;
    size_t base = (size_t)b * Mrows * HW + (size_t)mtb * 128 * HW + n0;
#pragma unroll
    for (int mt = 0; mt < 2; mt++) {
        int row0 = wm * 32 + mt * 16 + (lane >> 2);
#pragma unroll
        for (int nq = 0; nq < 8; nq++) {
            int col = wn * 64 + nq * 8 + (lane & 3) * 2;
            *reinterpret_cast<float2*>(&C[base + (size_t)row0 * HW + col]) =
                make_float2(acc[mt][nq][0], acc[mt][nq][1]);
            *reinterpret_cast<float2*>(&C[base + (size_t)(row0 + 8) * HW + col]) =
                make_float2(acc[mt][nq][2], acc[mt][nq][3]);
        }
    }
}
__global__ __launch_bounds__(256) void gemm_mma_pw1() { gemm_mma_body(g_a1, g_qkv); }
__global__ __launch_bounds__(256) void gemm_mma_pw2(float* __restrict__ out) {
    gemm_mma_body(g_a2, out);
}

// ---------------- 8x8 max pool k,v -> bf16 split ----------------------------
__global__ __launch_bounds__(256) void pool_kv() {
    int idx = blockIdx.x * 256 + threadIdx.x;
    int wk = idx & 15;
    int hk = (idx >> 4) & 15;
    int c = (idx >> 8) & 255;
    int which = (idx >> 16) & 1;
    int b = idx >> 17;
    int ch = 256 + which * 256 + c;
    const float* src = g_qkv + (((size_t)(b * 768 + ch)) << 14) + ((hk * 8) << 7) + wk * 8;
    float m = -3.402823466e+38f;
#pragma unroll
    for (int dy = 0; dy < 8; dy++)
#pragma unroll
        for (int dx = 0; dx < 8; dx++)
            m = fmaxf(m, src[(dy << 7) + dx]);
    int head = c & 3, d = c >> 2;
    int bh = b * HEADS + head, key = hk * 16 + wk;
    __nv_bfloat16 hi = __float2bfloat16_rn(m);
    __nv_bfloat16 lo = __float2bfloat16_rn(m - __bfloat162float(hi));
    if (which == 0) {
        g_kTh[(bh * NKEY + key) * DHEAD + d] = hi;
        g_kTl[(bh * NKEY + key) * DHEAD + d] = lo;
    } else {
        g_vTh[(bh * DHEAD + d) * NKEY + key] = hi;
        g_vTl[(bh * DHEAD + d) * NKEY + key] = lo;
    }
}

// ---------------- q transpose -> bf16 split [b,head][p][d] ------------------
__global__ __launch_bounds__(256) void transpose_q() {
    __shared__ float tile[64 * 65];
    int bx = blockIdx.x;
    int p0 = (bx & 255) << 6;
    int head = (bx >> 8) & 3;
    int b = bx >> 10;
    int t = threadIdx.x;
#pragma unroll
    for (int i = 0; i < 16; i++) {
        int idx = i * 256 + t;
        int d = idx >> 6, p = idx & 63;
        tile[d * 65 + p] = g_qkv[(((size_t)(b * 768 + d * 4 + head)) << 14) + p0 + p];
    }
    __syncthreads();
    size_t base = (((size_t)(b * HEADS + head)) << 14) + p0;
#pragma unroll
    for (int i = 0; i < 16; i++) {
        int idx = i * 256 + t;
        int p = idx >> 6, d = idx & 63;
        float v = tile[d * 65 + p];
        __nv_bfloat16 hi = __float2bfloat16_rn(v);
        g_qTh[(base + p) * 64 + d] = hi;
        g_qTl[(base + p) * 64 + d] = __float2bfloat16_rn(v - __bfloat162float(hi));
    }
}

// ================= HMMA attention (256 threads, fused rel+QK) ===============
#define AT_KH   0
#define AT_KL   36864
#define AT_VH   0
#define AT_VL   33792
#define AT_QH   73728
#define AT_QL   92160
#define AT_RH   110592
#define AT_RL   119808
#define AT_LWH  129024
#define AT_PM   162816
#define AT_PS   163840
#define AT_SMEM 164864

__global__ __launch_bounds__(256, 1) void attn_kernel(float* __restrict__ attn_out) {
    extern __shared__ char smc[];
    uint32_t sb = smem_u32(smc);
    int t = threadIdx.x, lane = t & 31, w = t >> 5;
    int wm = w >> 1, wn = w & 1;
    int hq = blockIdx.x, head = blockIdx.y, b = blockIdx.z;
    int bh = b * HEADS + head;
    int hq8 = hq >> 3;

    const __nv_bfloat16* kh = g_kTh + (size_t)bh * NKEY * DHEAD;
    const __nv_bfloat16* kl = g_kTl + (size_t)bh * NKEY * DHEAD;
    const __nv_bfloat16* qh = g_qTh + (((size_t)bh << 14) + (size_t)hq * 128) * 64;
    const __nv_bfloat16* ql = g_qTl + (((size_t)bh << 14) + (size_t)hq * 128) * 64;
#pragma unroll
    for (int i = 0; i < 8; i++) {
        int idx = i * 256 + t, row = idx >> 3, col = (idx & 7) * 8;
        cp16(sb + AT_KH + (row * 72 + col) * 2, kh + row * 64 + col);
        cp16(sb + AT_KL + (row * 72 + col) * 2, kl + row * 64 + col);
    }
#pragma unroll
    for (int i = 0; i < 4; i++) {
        int idx = i * 256 + t, row = idx >> 3, col = (idx & 7) * 8;
        cp16(sb + AT_QH + (row * 72 + col) * 2, qh + row * 64 + col);
        cp16(sb + AT_QL + (row * 72 + col) * 2, ql + row * 64 + col);
    }
#pragma unroll
    for (int i = 0; i < 2; i++) {
        int idx = i * 256 + t, row = idx >> 3, col = (idx & 7) * 8;
        cp16(sb + AT_RH + (row * 72 + col) * 2, g_Rh + row * 64 + col);
        cp16(sb + AT_RL + (row * 72 + col) * 2, g_Rl + row * 64 + col);
    }
    asm volatile("cp.async.commit_group;" ::: "memory");
    asm volatile("cp.async.wait_group 0;" ::: "memory");
    __syncthreads();

    uint32_t qsrc[3] = { sb + AT_QH, sb + AT_QL, sb + AT_QH };
    uint32_t rsrc[3] = { sb + AT_RH, sb + AT_RH, sb + AT_RL };
    uint32_t ksrc[3] = { sb + AT_KH, sb + AT_KH, sb + AT_KL };

    // ---- fused rel + QK mma: A-frags loaded once per (term,k16) ----
    float rc[2][4][4];
    float acc[2][16][4];
#pragma unroll
    for (int i = 0; i < 2; i++) {
#pragma unroll
        for (int j = 0; j < 4; j++)
#pragma unroll
            for (int q = 0; q < 4; q++) rc[i][j][q] = 0.f;
#pragma unroll
        for (int j = 0; j < 16; j++)
#pragma unroll
            for (int q = 0; q < 4; q++) acc[i][j][q] = 0.f;
    }
#pragma unroll
    for (int term = 0; term < 3; term++)
#pragma unroll
        for (int k16 = 0; k16 < 4; k16++) {
            uint32_t af[2][4];
#pragma unroll
            for (int mt = 0; mt < 2; mt++) {
                int row = wm * 32 + mt * 16 + (lane & 15);
                int col = k16 * 16 + (lane >> 4) * 8;
                ldsm4(af[mt], qsrc[term] + (row * 72 + col) * 2);
            }
            int kc = k16 * 16 + ((lane >> 3) & 1) * 8;
#pragma unroll
            for (int nq = 0; nq < 2; nq++) {      // rel: R cols wn*32..+31
                uint32_t bfr[4];
                int n = wn * 32 + nq * 16 + ((lane >> 4) << 3) + (lane & 7);
                ldsm4(bfr, rsrc[term] + (n * 72 + kc) * 2);
#pragma unroll
                for (int mt = 0; mt < 2; mt++) {
                    mma16816(rc[mt][nq * 2],     af[mt], bfr[0], bfr[1]);
                    mma16816(rc[mt][nq * 2 + 1], af[mt], bfr[2], bfr[3]);
                }
            }
#pragma unroll
            for (int nq = 0; nq < 8; nq++) {      // QK: keys wn*128..+127
                uint32_t bfr[4];
                int n = wn * 128 + nq * 16 + ((lane >> 4) << 3) + (lane & 7);
                ldsm4(bfr, ksrc[term] + (n * 72 + kc) * 2);
#pragma unroll
                for (int mt = 0; mt < 2; mt++) {
                    mma16816(acc[mt][nq * 2],     af[mt], bfr[0], bfr[1]);
                    mma16816(acc[mt][nq * 2 + 1], af[mt], bfr[2], bfr[3]);
                }
            }
        }
    // store rel logits to LWH
    {
        float* LWH = reinterpret_cast<float*>(smc + AT_LWH);
#pragma unroll
        for (int mt = 0; mt < 2; mt++) {
            int r0 = wm * 32 + mt * 16 + (lane >> 2);
#pragma unroll
            for (int nf = 0; nf < 4; nf++) {
                int c = wn * 32 + nf * 8 + (lane & 3) * 2;
                LWH[r0 * 66 + c]       = rc[mt][nf][0];
                LWH[r0 * 66 + c + 1]   = rc[mt][nf][1];
                LWH[(r0 + 8) * 66 + c]     = rc[mt][nf][2];
                LWH[(r0 + 8) * 66 + c + 1] = rc[mt][nf][3];
            }
        }
    }
    __syncthreads();   // K reads + LWH writes complete -> safe to overlay V

    {
        const __nv_bfloat16* vh = g_vTh + (size_t)bh * DHEAD * NKEY;
        const __nv_bfloat16* vl = g_vTl + (size_t)bh * DHEAD * NKEY;
#pragma unroll
        for (int i = 0; i < 8; i++) {
            int idx = i * 256 + t, row = idx >> 5, col = (idx & 31) * 8;
            cp16(sb + AT_VH + (row * 264 + col) * 2, vh + row * 256 + col);
            cp16(sb + AT_VL + (row * 264 + col) * 2, vl + row * 256 + col);
        }
        asm volatile("cp.async.commit_group;" ::: "memory");
    }

    float* LWH = reinterpret_cast<float*>(smc + AT_LWH);
    float* pm = reinterpret_cast<float*>(smc + AT_PM);
    float* ps = reinterpret_cast<float*>(smc + AT_PS);
    int r0t[2], r1t[2];
    float mx[2][2];
#pragma unroll
    for (int mt = 0; mt < 2; mt++) {
        r0t[mt] = wm * 32 + mt * 16 + (lane >> 2);
        r1t[mt] = r0t[mt] + 8;
        mx[mt][0] = -3.402823466e+38f; mx[mt][1] = -3.402823466e+38f;
        int wq80 = r0t[mt] >> 3, wq81 = r1t[mt] >> 3;
        const float* L0 = &LWH[r0t[mt] * 66];
        const float* L1 = &LWH[r1t[mt] * 66];
#pragma unroll
        for (int nf = 0; nf < 16; nf++) {
            int j = wn * 16 + nf;
            int hk = j >> 1;
            int c0 = (j & 1) * 8 + (lane & 3) * 2;
            float bh0 = L0[32 + hk - hq8 + 15];
            float bh1 = L1[32 + hk - hq8 + 15];
            float v0 = (acc[mt][nf][0] + bh0 + L0[c0 - wq80 + 15])     * 0.125f;
            float v1 = (acc[mt][nf][1] + bh0 + L0[c0 + 1 - wq80 + 15]) * 0.125f;
            float v2 = (acc[mt][nf][2] + bh1 + L1[c0 - wq81 + 15])     * 0.125f;
            float v3 = (acc[mt][nf][3] + bh1 + L1[c0 + 1 - wq81 + 15]) * 0.125f;
            acc[mt][nf][0] = v0; acc[mt][nf][1] = v1;
            acc[mt][nf][2] = v2; acc[mt][nf][3] = v3;
            mx[mt][0] = fmaxf(mx[mt][0], fmaxf(v0, v1));
            mx[mt][1] = fmaxf(mx[mt][1], fmaxf(v2, v3));
        }
#pragma unroll
        for (int o = 1; o <= 2; o <<= 1) {
            mx[mt][0] = fmaxf(mx[mt][0], __shfl_xor_sync(0xffffffffu, mx[mt][0], o));
            mx[mt][1] = fmaxf(mx[mt][1], __shfl_xor_sync(0xffffffffu, mx[mt][1], o));
        }
        pm[r0t[mt] * 2 + wn] = mx[mt][0];
        pm[r1t[mt] * 2 + wn] = mx[mt][1];
    }
    __syncthreads();
    float sum[2][2];
#pragma unroll
    for (int mt = 0; mt < 2; mt++) {
        float M0 = fmaxf(pm[r0t[mt] * 2], pm[r0t[mt] * 2 + 1]);
        float M1 = fmaxf(pm[r1t[mt] * 2], pm[r1t[mt] * 2 + 1]);
        sum[mt][0] = 0.f; sum[mt][1] = 0.f;
#pragma unroll
        for (int nf = 0; nf < 16; nf++) {
            float e0 = __expf(acc[mt][nf][0] - M0);
            float e1 = __expf(acc[mt][nf][1] - M0);
            float e2 = __expf(acc[mt][nf][2] - M1);
            float e3 = __expf(acc[mt][nf][3] - M1);
            acc[mt][nf][0] = e0; acc[mt][nf][1] = e1;
            acc[mt][nf][2] = e2; acc[mt][nf][3] = e3;
            sum[mt][0] += e0 + e1; sum[mt][1] += e2 + e3;
        }
#pragma unroll
        for (int o = 1; o <= 2; o <<= 1) {
            sum[mt][0] += __shfl_xor_sync(0xffffffffu, sum[mt][0], o);
            sum[mt][1] += __shfl_xor_sync(0xffffffffu, sum[mt][1], o);
        }
        ps[r0t[mt] * 2 + wn] = sum[mt][0];
        ps[r1t[mt] * 2 + wn] = sum[mt][1];
    }
    __syncthreads();

    size_t abase = ((size_t)bh * HW + (size_t)hq * 128) * NKEY;
    uint32_t uh[2][16], vh_[2][16], ul[2][16];
    uint32_t* vlS = reinterpret_cast<uint32_t*>(smc + AT_LWH) + t * 32;
#pragma unroll
    for (int mt = 0; mt < 2; mt++) {
        float inv0 = 1.f / (ps[r0t[mt] * 2] + ps[r0t[mt] * 2 + 1]);
        float inv1 = 1.f / (ps[r1t[mt] * 2] + ps[r1t[mt] * 2 + 1]);
#pragma unroll
        for (int nf = 0; nf < 16; nf++) {
            int j = wn * 16 + nf;
            int col = j * 8 + (lane & 3) * 2;
            float p0 = acc[mt][nf][0] * inv0, p1 = acc[mt][nf][1] * inv0;
            float p2 = acc[mt][nf][2] * inv1, p3 = acc[mt][nf][3] * inv1;
            *reinterpret_cast<float2*>(&attn_out[abase + (size_t)r0t[mt] * 256 + col]) =
                make_float2(p0, p1);
            *reinterpret_cast<float2*>(&attn_out[abase + (size_t)r1t[mt] * 256 + col]) =
                make_float2(p2, p3);
            uint32_t h01 = packbf(p0, p1), h23 = packbf(p2, p3);
            uh[mt][nf] = h01; vh_[mt][nf] = h23;
            __nv_bfloat162 hh01 = *reinterpret_cast<__nv_bfloat162*>(&h01);
            __nv_bfloat162 hh23 = *reinterpret_cast<__nv_bfloat162*>(&h23);
            ul[mt][nf] = packbf(p0 - __bfloat162float(hh01.x), p1 - __bfloat162float(hh01.y));
            vlS[mt * 16 + nf] = packbf(p2 - __bfloat162float(hh23.x), p3 - __bfloat162float(hh23.y));
        }
    }

    asm volatile("cp.async.wait_group 0;" ::: "memory");
    __syncthreads();
    float oacc[2][8][4];
#pragma unroll
    for (int i = 0; i < 2; i++)
#pragma unroll
        for (int j = 0; j < 8; j++)
#pragma unroll
            for (int q = 0; q < 4; q++) oacc[i][j][q] = 0.f;
#pragma unroll
    for (int kk = 0; kk < 8; kk++) {
        uint32_t afh[2][4], afl[2][4];
#pragma unroll
        for (int mt = 0; mt < 2; mt++) {
            afh[mt][0] = uh[mt][2 * kk];     afh[mt][1] = vh_[mt][2 * kk];
            afh[mt][2] = uh[mt][2 * kk + 1]; afh[mt][3] = vh_[mt][2 * kk + 1];
            afl[mt][0] = ul[mt][2 * kk];     afl[mt][1] = vlS[mt * 16 + 2 * kk];
            afl[mt][2] = ul[mt][2 * kk + 1]; afl[mt][3] = vlS[mt * 16 + 2 * kk + 1];
        }
        int kc = wn * 128 + kk * 16 + ((lane >> 3) & 1) * 8;
#pragma unroll
        for (int nq = 0; nq < 4; nq++) {
            int n = nq * 16 + ((lane >> 4) << 3) + (lane & 7);
            uint32_t bh_[4], bl_[4];
            ldsm4(bh_, sb + AT_VH + (n * 264 + kc) * 2);
            ldsm4(bl_, sb + AT_VL + (n * 264 + kc) * 2);
#pragma unroll
            for (int mt = 0; mt < 2; mt++) {
                mma16816(oacc[mt][nq * 2],     afh[mt], bh_[0], bh_[1]);
                mma16816(oacc[mt][nq * 2 + 1], afh[mt], bh_[2], bh_[3]);
                mma16816(oacc[mt][nq * 2],     afl[mt], bh_[0], bh_[1]);
                mma16816(oacc[mt][nq * 2 + 1], afl[mt], bh_[2], bh_[3]);
                mma16816(oacc[mt][nq * 2],     afh[mt], bl_[0], bl_[1]);
                mma16816(oacc[mt][nq * 2 + 1], afh[mt], bl_[2], bl_[3]);
            }
        }
    }

    float* oT = reinterpret_cast<float*>(smc + AT_LWH);   // [64][129]
    __syncthreads();
    if (wn == 0) {
#pragma unroll
        for (int mt = 0; mt < 2; mt++)
#pragma unroll
            for (int nf = 0; nf < 8; nf++) {
                int d = nf * 8 + (lane & 3) * 2;
                oT[d * 129 + r0t[mt]]       = oacc[mt][nf][0];
                oT[(d + 1) * 129 + r0t[mt]] = oacc[mt][nf][1];
                oT[d * 129 + r1t[mt]]       = oacc[mt][nf][2];
                oT[(d + 1) * 129 + r1t[mt]] = oacc[mt][nf][3];
            }
    }
    __syncthreads();
    if (wn == 1) {
#pragma unroll
        for (int mt = 0; mt < 2; mt++)
#pragma unroll
            for (int nf = 0; nf < 8; nf++) {
                int d = nf * 8 + (lane & 3) * 2;
                oT[d * 129 + r0t[mt]]       += oacc[mt][nf][0];
                oT[(d + 1) * 129 + r0t[mt]] += oacc[mt][nf][1];
                oT[d * 129 + r1t[mt]]       += oacc[mt][nf][2];
                oT[(d + 1) * 129 + r1t[mt]] += oacc[mt][nf][3];
            }
    }
    __syncthreads();
    for (int i = t; i < 64 * 128; i += 256) {
        int d = i >> 7, x = i & 127;
        g_y1[(((size_t)(b * CH + d * 4 + head)) * 128 + hq) * 128 + x] = oT[d * 129 + x];
    }
}

// ---------------------------------------------------------------------------
extern "C" void kernel_launch(void* const* d_in, const int* in_sizes, int n_in,
                              void* d_out, int out_size) {
    (void)in_sizes; (void)n_in; (void)out_size;
    const float* x    = (const float*)d_in[0];
    const float* dw1  = (const float*)d_in[1];
    const float* pw1  = (const float*)d_in[2];
    const float* relw = (const float*)d_in[3];
    const float* relh = (const float*)d_in[4];
    const float* dw2  = (const float*)d_in[5];
    const float* pw2  = (const float*)d_in[6];
    float* out  = (float*)d_out;
    float* attn = out + OUT_ELEMS;

    float* y2;
    cudaGetSymbolAddress((void**)&y2, g_y1);

    cudaFuncSetAttribute(attn_kernel, cudaFuncAttributeMaxDynamicSharedMemorySize, AT_SMEM);
    cudaFuncSetAttribute(gemm_mma_pw1, cudaFuncAttributeMaxDynamicSharedMemorySize, GEMM_SMEM);
    cudaFuncSetAttribute(gemm_mma_pw2, cudaFuncAttributeMaxDynamicSharedMemorySize, GEMM_SMEM);
    cudaFuncSetAttribute(dwt, cudaFuncAttributeMaxDynamicSharedMemorySize, DWT_SMEM);

    convert_w<<<1024, 256>>>(pw1, pw2);
    rel_build<<<16, 256>>>(relw, relh);
    dwt<<<dim3(16, 16, 4), 256, DWT_SMEM>>>(x, dw1);
    gemm_mma_pw1<<<dim3(6, 512), 256, GEMM_SMEM>>>();
    pool_kv<<<2048, 256>>>();
    transpose_q<<<4096, 256>>>();
    attn_kernel<<<dim3(128, HEADS, BATCH), 256, AT_SMEM>>>(attn);
    dwt<<<dim3(16, 16, 4), 256, DWT_SMEM>>>(y2, dw2);
    gemm_mma_pw2<<<dim3(2, 512), 256, GEMM_SMEM>>>(out);
}